// round 1
// baseline (speedup 1.0000x reference)
#include <cuda_runtime.h>
#include <cuda_bf16.h>
#include <cuda_fp8.h>
#include <mma.h>
#include <cstdint>

using namespace nvcuda;

// Problem sizes
#define TOK 16384
#define HID 2048
#define Y4SZ (TOK * HID)         // 33554432
#define SCSZ (TOK * (HID / 128)) // 262144

// ---------------- scratch (device globals: allocation-free) ----------------
__device__ __nv_bfloat16 g_Ahi[(size_t)TOK * HID];      // 64 MB
__device__ __nv_bfloat16 g_Alo[(size_t)TOK * HID];      // 64 MB
__device__ __nv_bfloat16 g_Whi[(size_t)3 * HID * HID];  // 25 MB
__device__ __nv_bfloat16 g_Wlo[(size_t)3 * HID * HID];  // 25 MB
__device__ float         g_C[(size_t)TOK * HID];        // 128 MB
__device__ float         g_resid[(size_t)TOK * HID];    // 128 MB

// ---------------- helpers ----------------
__device__ __forceinline__ float block_sum_256(float v) {
    __shared__ float red[8];
    int lane = threadIdx.x & 31, warp = threadIdx.x >> 5;
#pragma unroll
    for (int o = 16; o; o >>= 1) v += __shfl_xor_sync(0xffffffffu, v, o);
    if (lane == 0) red[warp] = v;
    __syncthreads();
    if (threadIdx.x == 0) {
        float t = 0.f;
#pragma unroll
        for (int i = 0; i < 8; i++) t += red[i];
        red[0] = t;
    }
    __syncthreads();
    return red[0];
}

// exact ceil-to-power-of-2 of a positive normal float (matches exp2(ceil(log2(x))))
__device__ __forceinline__ float pow2_ceil(float s0) {
    uint32_t ub = __float_as_uint(s0);
    if (ub & 0x007fffffu) ub = (((ub >> 23) & 0xffu) + 1u) << 23;
    return __uint_as_float(ub);
}

// ---------------- W split: w(fp32) -> Whi + Wlo (bf16) ----------------
__global__ void __launch_bounds__(256) wsplit_kernel(const float* __restrict__ w) {
    size_t i4 = ((size_t)blockIdx.x * 256 + threadIdx.x) * 4;
    float4 v = *(const float4*)&w[i4];
    float vv[4] = {v.x, v.y, v.z, v.w};
    uint2 uh, ul;
    __nv_bfloat16* hp = reinterpret_cast<__nv_bfloat16*>(&uh);
    __nv_bfloat16* lp = reinterpret_cast<__nv_bfloat16*>(&ul);
#pragma unroll
    for (int i = 0; i < 4; i++) {
        __nv_bfloat16 hi = __float2bfloat16(vv[i]);
        hp[i] = hi;
        lp[i] = __float2bfloat16(vv[i] - __bfloat162float(hi));
    }
    *(uint2*)&g_Whi[i4] = uh;
    *(uint2*)&g_Wlo[i4] = ul;
}

// ---------------- prep: z = relu(x); y = rmsnorm(z)*nw0; split to Ahi/Alo ----------------
__global__ void __launch_bounds__(256) prep_kernel(const float* __restrict__ x,
                                                   const float* __restrict__ nw0) {
    int row = blockIdx.x, tid = threadIdx.x;
    size_t base = (size_t)row * HID + tid * 8;
    float4 a = *(const float4*)&x[base];
    float4 b = *(const float4*)&x[base + 4];
    float v[8] = {a.x, a.y, a.z, a.w, b.x, b.y, b.z, b.w};
    float ss = 0.f;
#pragma unroll
    for (int j = 0; j < 8; j++) { v[j] = fmaxf(v[j], 0.f); ss += v[j] * v[j]; }
    float tot = block_sum_256(ss);
    float inv = 1.0f / sqrtf(tot * (1.0f / HID) + 1e-5f);
    uint4 uh, ul;
    __nv_bfloat16* hp = reinterpret_cast<__nv_bfloat16*>(&uh);
    __nv_bfloat16* lp = reinterpret_cast<__nv_bfloat16*>(&ul);
#pragma unroll
    for (int j = 0; j < 8; j++) {
        float y = v[j] * inv * nw0[tid * 8 + j];
        __nv_bfloat16 hi = __float2bfloat16(y);
        hp[j] = hi;
        lp[j] = __float2bfloat16(y - __bfloat162float(hi));
    }
    *(uint4*)&g_Ahi[base] = uh;
    *(uint4*)&g_Alo[base] = ul;
}

// ---------------- GEMM: C = A @ W  (bf16 split, fp32 accum) ----------------
// TERMS==3: Ahi*Bhi + Ahi*Blo + Alo*Bhi   (fp32 A, fp32 W)
// TERMS==2: A*Bhi + A*Blo                 (A exactly bf16, fp32 W)
template <int TERMS>
__global__ void __launch_bounds__(256) gemm_kernel(int widx) {
    constexpr int BM = 128, BN = 128, BK = 32, LDA = 40, LDB = 136;
    __shared__ __align__(16) __nv_bfloat16 sAhi[BM * LDA];
    __shared__ __align__(16) __nv_bfloat16 sBhi[BK * LDB];
    __shared__ __align__(16) __nv_bfloat16 sBlo[BK * LDB];
    __shared__ __align__(16) __nv_bfloat16 sAlo[TERMS == 3 ? BM * LDA : 8];

    const __nv_bfloat16* gBhi = g_Whi + (size_t)widx * HID * HID;
    const __nv_bfloat16* gBlo = g_Wlo + (size_t)widx * HID * HID;

    int m0 = blockIdx.y * BM, n0 = blockIdx.x * BN;
    int tid = threadIdx.x;
    int wid = tid >> 5;
    int wm = wid >> 1, wn = wid & 1;  // 4x2 warp grid, warp tile 32x64

    wmma::fragment<wmma::accumulator, 16, 16, 16, float> acc[2][4];
#pragma unroll
    for (int i = 0; i < 2; i++)
#pragma unroll
        for (int j = 0; j < 4; j++) wmma::fill_fragment(acc[i][j], 0.0f);

    for (int k0 = 0; k0 < HID; k0 += BK) {
#pragma unroll
        for (int it = 0; it < 2; it++) {
            int c = tid + it * 256;
            int ar = c >> 2, ac = (c & 3) * 8;
            *(uint4*)&sAhi[ar * LDA + ac] =
                *(const uint4*)&g_Ahi[(size_t)(m0 + ar) * HID + k0 + ac];
            if constexpr (TERMS == 3)
                *(uint4*)&sAlo[ar * LDA + ac] =
                    *(const uint4*)&g_Alo[(size_t)(m0 + ar) * HID + k0 + ac];
            int br = c >> 4, bc = (c & 15) * 8;
            *(uint4*)&sBhi[br * LDB + bc] =
                *(const uint4*)&gBhi[(size_t)(k0 + br) * HID + n0 + bc];
            *(uint4*)&sBlo[br * LDB + bc] =
                *(const uint4*)&gBlo[(size_t)(k0 + br) * HID + n0 + bc];
        }
        __syncthreads();
#pragma unroll
        for (int ks = 0; ks < BK; ks += 16) {
            wmma::fragment<wmma::matrix_a, 16, 16, 16, __nv_bfloat16, wmma::row_major> ah[2], al[2];
            wmma::fragment<wmma::matrix_b, 16, 16, 16, __nv_bfloat16, wmma::row_major> bh[4], bl[4];
#pragma unroll
            for (int i = 0; i < 2; i++) {
                wmma::load_matrix_sync(ah[i], &sAhi[(wm * 32 + i * 16) * LDA + ks], LDA);
                if constexpr (TERMS == 3)
                    wmma::load_matrix_sync(al[i], &sAlo[(wm * 32 + i * 16) * LDA + ks], LDA);
            }
#pragma unroll
            for (int j = 0; j < 4; j++) {
                wmma::load_matrix_sync(bh[j], &sBhi[ks * LDB + wn * 64 + j * 16], LDB);
                wmma::load_matrix_sync(bl[j], &sBlo[ks * LDB + wn * 64 + j * 16], LDB);
            }
#pragma unroll
            for (int i = 0; i < 2; i++)
#pragma unroll
                for (int j = 0; j < 4; j++) {
                    wmma::mma_sync(acc[i][j], ah[i], bh[j], acc[i][j]);
                    wmma::mma_sync(acc[i][j], ah[i], bl[j], acc[i][j]);
                    if constexpr (TERMS == 3)
                        wmma::mma_sync(acc[i][j], al[i], bh[j], acc[i][j]);
                }
        }
        __syncthreads();
    }
#pragma unroll
    for (int i = 0; i < 2; i++)
#pragma unroll
        for (int j = 0; j < 4; j++)
            wmma::store_matrix_sync(
                &g_C[(size_t)(m0 + wm * 32 + i * 16) * HID + n0 + wn * 64 + j * 16],
                acc[i][j], HID, wmma::mem_row_major);
}

// ---------------- epilogue: resid add + rmsnorm + (quant | output) ----------------
// MODE 1: resid_src = relu(x);  write resid, quant -> g_Ahi(bf16), scales -> scale_out
// MODE 2: resid_src = g_resid;  write resid, quant -> g_Ahi(bf16), scales -> scale_out
// MODE 3: resid_src = g_resid;  write y4 -> y_out
template <int MODE>
__global__ void __launch_bounds__(256) epi_kernel(const float* __restrict__ x,
                                                  const float* __restrict__ nw,
                                                  float* __restrict__ scale_out,
                                                  float* __restrict__ y_out) {
    int row = blockIdx.x, tid = threadIdx.x;
    size_t base = (size_t)row * HID + tid * 8;

    float4 c0 = *(const float4*)&g_C[base];
    float4 c1 = *(const float4*)&g_C[base + 4];
    float cv[8] = {c0.x, c0.y, c0.z, c0.w, c1.x, c1.y, c1.z, c1.w};

    float r[8];
    if constexpr (MODE == 1) {
        float4 x0 = *(const float4*)&x[base];
        float4 x1 = *(const float4*)&x[base + 4];
        float xv[8] = {x0.x, x0.y, x0.z, x0.w, x1.x, x1.y, x1.z, x1.w};
#pragma unroll
        for (int j = 0; j < 8; j++) r[j] = cv[j] + fmaxf(xv[j], 0.f);
    } else {
        float4 r0 = *(const float4*)&g_resid[base];
        float4 r1 = *(const float4*)&g_resid[base + 4];
        float rv[8] = {r0.x, r0.y, r0.z, r0.w, r1.x, r1.y, r1.z, r1.w};
#pragma unroll
        for (int j = 0; j < 8; j++) r[j] = cv[j] + rv[j];
    }
    if constexpr (MODE < 3) {
        float4 o0 = make_float4(r[0], r[1], r[2], r[3]);
        float4 o1 = make_float4(r[4], r[5], r[6], r[7]);
        *(float4*)&g_resid[base] = o0;
        *(float4*)&g_resid[base + 4] = o1;
    }

    float ss = 0.f;
#pragma unroll
    for (int j = 0; j < 8; j++) ss += r[j] * r[j];
    float tot = block_sum_256(ss);
    float inv = 1.0f / sqrtf(tot * (1.0f / HID) + 1e-5f);

    float y[8];
#pragma unroll
    for (int j = 0; j < 8; j++) y[j] = r[j] * inv * nw[tid * 8 + j];

    if constexpr (MODE == 3) {
        *(float4*)&y_out[base] = make_float4(y[0], y[1], y[2], y[3]);
        *(float4*)&y_out[base + 4] = make_float4(y[4], y[5], y[6], y[7]);
    } else {
        // per-128-group amax: thread's 8 cols all within group tid/16; 16 threads/group
        float a = 0.f;
#pragma unroll
        for (int j = 0; j < 8; j++) a = fmaxf(a, fabsf(y[j]));
#pragma unroll
        for (int o = 8; o; o >>= 1) a = fmaxf(a, __shfl_xor_sync(0xffffffffu, a, o));

        float s0 = fmaxf(a, 1e-10f) / 448.0f;
        float scale = pow2_ceil(s0);
        if ((tid & 15) == 0) scale_out[(size_t)row * 16 + (tid >> 4)] = scale;

        float rinv = 1.0f / scale;  // exact: scale is a power of 2
        uint4 uh;
        __nv_bfloat16* hp = reinterpret_cast<__nv_bfloat16*>(&uh);
#pragma unroll
        for (int j = 0; j < 8; j++) {
            float q = y[j] * rinv;
            q = fminf(fmaxf(q, -448.f), 448.f);
            __nv_fp8_e4m3 q8(q);                       // RN + satfinite, matches jnp astype
            hp[j] = __float2bfloat16((float)q8);       // fp8 values are exact in bf16
        }
        *(uint4*)&g_Ahi[base] = uh;
    }
}

// ---------------- launch ----------------
extern "C" void kernel_launch(void* const* d_in, const int* in_sizes, int n_in,
                              void* d_out, int out_size) {
    (void)in_sizes; (void)n_in; (void)out_size;
    const float* x      = (const float*)d_in[0];  // [16384, 2048]
    const float* norm_w = (const float*)d_in[1];  // [4, 2048]
    const float* w      = (const float*)d_in[2];  // [3, 2048, 2048]
    float* out = (float*)d_out;                   // y4 | y2_s | y3_s

    float* y4_out = out;
    float* y2s    = out + Y4SZ;
    float* y3s    = out + Y4SZ + SCSZ;

    dim3 ggrid(HID / 128, TOK / 128);  // (16, 128)

    wsplit_kernel<<<(3 * HID * HID) / (4 * 256), 256>>>(w);
    prep_kernel<<<TOK, 256>>>(x, norm_w);
    gemm_kernel<3><<<ggrid, 256>>>(0);
    epi_kernel<1><<<TOK, 256>>>(x, norm_w + HID, y2s, nullptr);
    gemm_kernel<2><<<ggrid, 256>>>(1);
    epi_kernel<2><<<TOK, 256>>>(nullptr, norm_w + 2 * HID, y3s, nullptr);
    gemm_kernel<2><<<ggrid, 256>>>(2);
    epi_kernel<3><<<TOK, 256>>>(nullptr, norm_w + 3 * HID, nullptr, y4_out);
}

// round 5
// speedup vs baseline: 1.9230x; 1.9230x over previous
#include <cuda_runtime.h>
#include <cuda_bf16.h>
#include <cuda_fp8.h>
#include <cstdint>

// Problem sizes
#define TOK 16384
#define HID 2048
#define Y4SZ (TOK * HID)
#define SCSZ (TOK * (HID / 128))

// ---------------- scratch (device globals: allocation-free) ----------------
__device__ __nv_bfloat16 g_Ahi[(size_t)TOK * HID];       // 64 MB
__device__ __nv_bfloat16 g_Alo[(size_t)TOK * HID];       // 64 MB
__device__ __nv_bfloat16 g_WThi[(size_t)3 * HID * HID];  // 25 MB, [N,K] K-major
__device__ __nv_bfloat16 g_WTlo[(size_t)3 * HID * HID];  // 25 MB
__device__ float         g_C[(size_t)TOK * HID];         // 128 MB
__device__ float         g_resid[(size_t)TOK * HID];     // 128 MB

// ---------------- PTX helpers (baseline ISA only: sm_80-level) ----------------
__device__ __forceinline__ uint32_t smem_u32(const void* p) {
    uint32_t a;
    asm("{ .reg .u64 t; cvta.to.shared.u64 t, %1; cvt.u32.u64 %0, t; }" : "=r"(a) : "l"(p));
    return a;
}
__device__ __forceinline__ void cp16(uint32_t s, const void* g) {
    asm volatile("cp.async.cg.shared.global [%0], [%1], 16;" :: "r"(s), "l"(g));
}
__device__ __forceinline__ void cp_commit() { asm volatile("cp.async.commit_group;" ::: "memory"); }
__device__ __forceinline__ void cp_wait1()  { asm volatile("cp.async.wait_group 1;"  ::: "memory"); }

__device__ __forceinline__ void ldsm4(uint32_t* r, uint32_t addr) {
    asm volatile("ldmatrix.sync.aligned.m8n8.x4.shared.b16 {%0,%1,%2,%3}, [%4];"
                 : "=r"(r[0]), "=r"(r[1]), "=r"(r[2]), "=r"(r[3]) : "r"(addr));
}
__device__ __forceinline__ void mma16816(float* d, const uint32_t* a, uint32_t b0, uint32_t b1) {
    asm volatile(
        "mma.sync.aligned.m16n8k16.row.col.f32.bf16.bf16.f32 "
        "{%0,%1,%2,%3}, {%4,%5,%6,%7}, {%8,%9}, {%0,%1,%2,%3};"
        : "+f"(d[0]), "+f"(d[1]), "+f"(d[2]), "+f"(d[3])
        : "r"(a[0]), "r"(a[1]), "r"(a[2]), "r"(a[3]), "r"(b0), "r"(b1));
}

// ---------------- reduction / quant helpers ----------------
__device__ __forceinline__ float block_sum_256(float v) {
    __shared__ float red[8];
    int lane = threadIdx.x & 31, warp = threadIdx.x >> 5;
#pragma unroll
    for (int o = 16; o; o >>= 1) v += __shfl_xor_sync(0xffffffffu, v, o);
    if (lane == 0) red[warp] = v;
    __syncthreads();
    if (threadIdx.x == 0) {
        float t = 0.f;
#pragma unroll
        for (int i = 0; i < 8; i++) t += red[i];
        red[0] = t;
    }
    __syncthreads();
    return red[0];
}
__device__ __forceinline__ float pow2_ceil(float s0) {
    uint32_t ub = __float_as_uint(s0);
    if (ub & 0x007fffffu) ub = (((ub >> 23) & 0xffu) + 1u) << 23;
    return __uint_as_float(ub);
}

// ---------------- W split + transpose: w[m][k][n] -> g_WT{hi,lo}[m][n][k] ----------------
__global__ void __launch_bounds__(256) wsplit_kernel(const float* __restrict__ w) {
    __shared__ float t[32][33];
    int m = blockIdx.z;
    int tx = threadIdx.x & 31, ty = threadIdx.x >> 5;  // 32x8
    int kbase = blockIdx.y * 32, nbase = blockIdx.x * 32;
    const float* src = w + (size_t)m * HID * HID;
#pragma unroll
    for (int i = 0; i < 4; i++)
        t[ty + i * 8][tx] = src[(size_t)(kbase + ty + i * 8) * HID + nbase + tx];
    __syncthreads();
    size_t ob = (size_t)m * HID * HID;
#pragma unroll
    for (int i = 0; i < 4; i++) {
        int n = nbase + ty + i * 8, k = kbase + tx;
        float v = t[tx][ty + i * 8];
        __nv_bfloat16 hi = __float2bfloat16(v);
        g_WThi[ob + (size_t)n * HID + k] = hi;
        g_WTlo[ob + (size_t)n * HID + k] = __float2bfloat16(v - __bfloat162float(hi));
    }
}

// ---------------- prep: z = relu(x); y = rmsnorm(z)*nw0; split to Ahi/Alo ----------------
__global__ void __launch_bounds__(256) prep_kernel(const float* __restrict__ x,
                                                   const float* __restrict__ nw0) {
    int row = blockIdx.x, tid = threadIdx.x;
    size_t base = (size_t)row * HID + tid * 8;
    float4 a = *(const float4*)&x[base];
    float4 b = *(const float4*)&x[base + 4];
    float v[8] = {a.x, a.y, a.z, a.w, b.x, b.y, b.z, b.w};
    float ss = 0.f;
#pragma unroll
    for (int j = 0; j < 8; j++) { v[j] = fmaxf(v[j], 0.f); ss += v[j] * v[j]; }
    float tot = block_sum_256(ss);
    float inv = 1.0f / sqrtf(tot * (1.0f / HID) + 1e-5f);
    uint4 uh, ul;
    __nv_bfloat16* hp = reinterpret_cast<__nv_bfloat16*>(&uh);
    __nv_bfloat16* lp = reinterpret_cast<__nv_bfloat16*>(&ul);
#pragma unroll
    for (int j = 0; j < 8; j++) {
        float y = v[j] * inv * nw0[tid * 8 + j];
        __nv_bfloat16 hi = __float2bfloat16(y);
        hp[j] = hi;
        lp[j] = __float2bfloat16(y - __bfloat162float(hi));
    }
    *(uint4*)&g_Ahi[base] = uh;
    *(uint4*)&g_Alo[base] = ul;
}

// ---------------- mma.sync GEMM: C[M,N] = A[M,K] @ WT[N,K]^T, split-compensated --------
// CTA 128x128, BK=64, 3-stage cp.async pipeline, 8 warps (2x4), warp tile 64x32.
// TERMS==3: Ahi*Bhi + Ahi*Blo + Alo*Bhi ; TERMS==2: A*Bhi + A*Blo
#define BK 64
#define STAGES 3

template <int TERMS>
struct StageCfg {
    static constexpr int OFF_ALO = 16384;
    static constexpr int OFF_BHI = (TERMS == 3) ? 32768 : 16384;
    static constexpr int OFF_BLO = OFF_BHI + 16384;
    static constexpr int STAGE   = OFF_BLO + 16384;  // 64K (T3) / 48K (T2)
};

template <int TERMS>
__device__ __forceinline__ void load_stage(uint32_t b, const __nv_bfloat16* A,
                                           const __nv_bfloat16* AL, const __nv_bfloat16* BH,
                                           const __nv_bfloat16* BL, int m0, int n0, int k0,
                                           int tid) {
    using C = StageCfg<TERMS>;
#pragma unroll
    for (int i = 0; i < 4; i++) {  // 128 rows x 8 chunks of 16B
        int idx = tid + i * 256;
        int r = idx >> 3, c = idx & 7;
        uint32_t so = r * 128 + ((c ^ (r & 7)) << 4);
        const size_t go = (size_t)r * HID + k0 + c * 8;
        cp16(b + so, A + (size_t)m0 * HID + go);
        if constexpr (TERMS == 3) cp16(b + C::OFF_ALO + so, AL + (size_t)m0 * HID + go);
        cp16(b + C::OFF_BHI + so, BH + (size_t)n0 * HID + go);
        cp16(b + C::OFF_BLO + so, BL + (size_t)n0 * HID + go);
    }
    cp_commit();
}

template <int TERMS>
__global__ void __launch_bounds__(256, 1) gemm_mma(int widx) {
    using C = StageCfg<TERMS>;
    extern __shared__ char smem[];
    const int tid = threadIdx.x, lane = tid & 31, wid = tid >> 5;
    const int wm = wid >> 2, wn = wid & 3;  // 2x4 warps, warp tile 64x32
    const int n0 = blockIdx.x * 128, m0 = blockIdx.y * 128;

    uint32_t sb = smem_u32(smem);

    const __nv_bfloat16* A  = g_Ahi;
    const __nv_bfloat16* AL = g_Alo;
    const __nv_bfloat16* BH = g_WThi + (size_t)widx * HID * HID;
    const __nv_bfloat16* BL = g_WTlo + (size_t)widx * HID * HID;

    float acc[4][4][4];
#pragma unroll
    for (int i = 0; i < 4; i++)
#pragma unroll
        for (int j = 0; j < 4; j++)
#pragma unroll
            for (int r = 0; r < 4; r++) acc[i][j][r] = 0.f;

    // prologue: stages 0,1
    load_stage<TERMS>(sb, A, AL, BH, BL, m0, n0, 0, tid);
    load_stage<TERMS>(sb + C::STAGE, A, AL, BH, BL, m0, n0, BK, tid);

    // precomputed ldmatrix lane addressing (within a stage, swizzled)
    // A/AL: rows m-dim; lane l: row = (l&15), chunk base (l>>4)
    const int a_row = wm * 64 + (lane & 15);
    const uint32_t a_cchi = (uint32_t)(lane >> 4);
    // B: rows n-dim; lane l: row = (l&7) + ((l>>4)<<3), chunk base ((l>>3)&1)
    const int b_row = wn * 32 + (lane & 7) + ((lane >> 4) << 3);
    const uint32_t b_cchi = (uint32_t)((lane >> 3) & 1);

    const int NIT = HID / BK;  // 32
    for (int it = 0; it < NIT; it++) {
        const int s = it % STAGES;
        cp_wait1();
        __syncthreads();
        if (it + 2 < NIT)
            load_stage<TERMS>(sb + ((it + 2) % STAGES) * C::STAGE, A, AL, BH, BL, m0, n0,
                              (it + 2) * BK, tid);
        else
            cp_commit();

        const uint32_t st = sb + s * C::STAGE;
#pragma unroll
        for (int kk = 0; kk < BK / 16; kk++) {
            uint32_t a[4][4], al[TERMS == 3 ? 4 : 1][4];
#pragma unroll
            for (int i = 0; i < 4; i++) {
                int row = a_row + i * 16;
                uint32_t cc = kk * 2 + a_cchi;
                uint32_t ad = st + row * 128 + ((cc ^ (row & 7)) << 4);
                ldsm4(a[i], ad);
                if constexpr (TERMS == 3) ldsm4(al[i], ad + C::OFF_ALO);
            }
            uint32_t bh[2][4], bl[2][4];
#pragma unroll
            for (int g = 0; g < 2; g++) {
                int row = b_row + g * 16;
                uint32_t cc = kk * 2 + b_cchi;
                uint32_t so = row * 128 + ((cc ^ (row & 7)) << 4);
                ldsm4(bh[g], st + C::OFF_BHI + so);
                ldsm4(bl[g], st + C::OFF_BLO + so);
            }
            // frag j (n8): group g=j>>1; regs {r0,r1} (j even) or {r2,r3} (j odd)
#pragma unroll
            for (int i = 0; i < 4; i++) {
#pragma unroll
                for (int j = 0; j < 4; j++) {
                    const uint32_t* bhf = bh[j >> 1];
                    const uint32_t* blf = bl[j >> 1];
                    int o = (j & 1) * 2;
                    mma16816(acc[i][j], a[i], bhf[o], bhf[o + 1]);
                    mma16816(acc[i][j], a[i], blf[o], blf[o + 1]);
                    if constexpr (TERMS == 3) mma16816(acc[i][j], al[i], bhf[o], bhf[o + 1]);
                }
            }
        }
    }

    // epilogue: regs -> g_C
    const int er = m0 + wm * 64 + (lane >> 2);
    const int ec = n0 + wn * 32 + 2 * (lane & 3);
#pragma unroll
    for (int i = 0; i < 4; i++) {
#pragma unroll
        for (int j = 0; j < 4; j++) {
            float* p0 = &g_C[(size_t)(er + i * 16) * HID + ec + j * 8];
            float* p1 = &g_C[(size_t)(er + i * 16 + 8) * HID + ec + j * 8];
            *(float2*)p0 = make_float2(acc[i][j][0], acc[i][j][1]);
            *(float2*)p1 = make_float2(acc[i][j][2], acc[i][j][3]);
        }
    }
}

// ---------------- epilogue: resid add + rmsnorm + (quant | output) ----------------
template <int MODE>
__global__ void __launch_bounds__(256) epi_kernel(const float* __restrict__ x,
                                                  const float* __restrict__ nw,
                                                  float* __restrict__ scale_out,
                                                  float* __restrict__ y_out) {
    int row = blockIdx.x, tid = threadIdx.x;
    size_t base = (size_t)row * HID + tid * 8;

    float4 c0 = *(const float4*)&g_C[base];
    float4 c1 = *(const float4*)&g_C[base + 4];
    float cv[8] = {c0.x, c0.y, c0.z, c0.w, c1.x, c1.y, c1.z, c1.w};

    float r[8];
    if constexpr (MODE == 1) {
        float4 x0 = *(const float4*)&x[base];
        float4 x1 = *(const float4*)&x[base + 4];
        float xv[8] = {x0.x, x0.y, x0.z, x0.w, x1.x, x1.y, x1.z, x1.w};
#pragma unroll
        for (int j = 0; j < 8; j++) r[j] = cv[j] + fmaxf(xv[j], 0.f);
    } else {
        float4 r0 = *(const float4*)&g_resid[base];
        float4 r1 = *(const float4*)&g_resid[base + 4];
        float rv[8] = {r0.x, r0.y, r0.z, r0.w, r1.x, r1.y, r1.z, r1.w};
#pragma unroll
        for (int j = 0; j < 8; j++) r[j] = cv[j] + rv[j];
    }
    if constexpr (MODE < 3) {
        *(float4*)&g_resid[base]     = make_float4(r[0], r[1], r[2], r[3]);
        *(float4*)&g_resid[base + 4] = make_float4(r[4], r[5], r[6], r[7]);
    }

    float ss = 0.f;
#pragma unroll
    for (int j = 0; j < 8; j++) ss += r[j] * r[j];
    float tot = block_sum_256(ss);
    float inv = 1.0f / sqrtf(tot * (1.0f / HID) + 1e-5f);

    float y[8];
#pragma unroll
    for (int j = 0; j < 8; j++) y[j] = r[j] * inv * nw[tid * 8 + j];

    if constexpr (MODE == 3) {
        *(float4*)&y_out[base]     = make_float4(y[0], y[1], y[2], y[3]);
        *(float4*)&y_out[base + 4] = make_float4(y[4], y[5], y[6], y[7]);
    } else {
        float a = 0.f;
#pragma unroll
        for (int j = 0; j < 8; j++) a = fmaxf(a, fabsf(y[j]));
#pragma unroll
        for (int o = 8; o; o >>= 1) a = fmaxf(a, __shfl_xor_sync(0xffffffffu, a, o));

        float scale = pow2_ceil(fmaxf(a, 1e-10f) / 448.0f);
        if ((tid & 15) == 0) scale_out[(size_t)row * 16 + (tid >> 4)] = scale;

        float rinv = 1.0f / scale;  // exact: power of 2
        uint4 uh;
        __nv_bfloat16* hp = reinterpret_cast<__nv_bfloat16*>(&uh);
#pragma unroll
        for (int j = 0; j < 8; j++) {
            float q = y[j] * rinv;
            q = fminf(fmaxf(q, -448.f), 448.f);
            __nv_fp8_e4m3 q8(q);
            hp[j] = __float2bfloat16((float)q8);  // fp8 values exact in bf16
        }
        *(uint4*)&g_Ahi[base] = uh;
    }
}

// ---------------- launch ----------------
extern "C" void kernel_launch(void* const* d_in, const int* in_sizes, int n_in,
                              void* d_out, int out_size) {
    (void)in_sizes; (void)n_in; (void)out_size;
    const float* x      = (const float*)d_in[0];
    const float* norm_w = (const float*)d_in[1];
    const float* w      = (const float*)d_in[2];
    float* out = (float*)d_out;

    float* y4_out = out;
    float* y2s    = out + Y4SZ;
    float* y3s    = out + Y4SZ + SCSZ;

    const int SMEM3 = STAGES * StageCfg<3>::STAGE;  // 196608
    const int SMEM2 = STAGES * StageCfg<2>::STAGE;  // 147456
    cudaFuncSetAttribute(gemm_mma<3>, cudaFuncAttributeMaxDynamicSharedMemorySize, SMEM3);
    cudaFuncSetAttribute(gemm_mma<2>, cudaFuncAttributeMaxDynamicSharedMemorySize, SMEM2);

    dim3 ggrid(HID / 128, TOK / 128);  // (16, 128): N-tile fastest -> W stays L2-hot

    wsplit_kernel<<<dim3(64, 64, 3), 256>>>(w);
    prep_kernel<<<TOK, 256>>>(x, norm_w);
    gemm_mma<3><<<ggrid, 256, SMEM3>>>(0);
    epi_kernel<1><<<TOK, 256>>>(x, norm_w + HID, y2s, nullptr);
    gemm_mma<2><<<ggrid, 256, SMEM2>>>(1);
    epi_kernel<2><<<TOK, 256>>>(nullptr, norm_w + 2 * HID, y3s, nullptr);
    gemm_mma<2><<<ggrid, 256, SMEM2>>>(2);
    epi_kernel<3><<<TOK, 256>>>(nullptr, norm_w + 3 * HID, nullptr, y4_out);
}